// round 1
// baseline (speedup 1.0000x reference)
#include <cuda_runtime.h>
#include <math.h>

#define WNB   64      // windows (Bn)
#define LSEQ  512
#define CM    96      // d_model
#define DI    192     // d_inner
#define DS    16      // d_state
#define DR    6       // dt_rank
#define E2    384     // 2*d_inner
#define NPOS  (WNB*LSEQ)   // 32768
#define NSPAT 32768        // 32*32*32

// ---------------- scratch (device globals; no allocation allowed) -------------
__device__ __align__(16) float g_xn[NPOS*CM];        // (m, c)       12.6 MB
__device__ __align__(16) float g_xz[NPOS*E2];        // (m, e)       50 MB
__device__ __align__(16) float g_u[3][NPOS*DI];      // (br, m_scan, d) 75 MB
__device__ __align__(16) float g_delta[3][NPOS*DI];  // 75 MB
__device__ __align__(16) float g_Bm[3][NPOS*DS];     // 6.3 MB
__device__ __align__(16) float g_Cm[3][NPOS*DS];     // 6.3 MB
__device__ __align__(16) float g_y[3][NPOS*DI];      // (br, m_orig, d) 75 MB
__device__ float g_mean[CM];
__device__ float g_gate[CM];

__device__ __forceinline__ float siluf(float v){ return v / (1.f + __expf(-v)); }
__device__ __forceinline__ float softplusf(float v){ return v > 15.f ? v : log1pf(__expf(v)); }

// scan-order t  ->  original window position l
__device__ __forceinline__ int perm_idx(int br, int t){
    if (br == 0) return t;
    if (br == 1) return 511 - t;
    return ((t & 7) << 6) + (t >> 3);   // slice: orig = (t%8)*64 + t/8
}

// ---------------- K1: layernorm over C (gathers window partition) -------------
__global__ void ln_kernel(const float* __restrict__ x,
                          const float* __restrict__ lnw,
                          const float* __restrict__ lnb){
    int s = blockIdx.x*blockDim.x + threadIdx.x;   // spatial 0..32767
    float sum = 0.f, sq = 0.f;
    #pragma unroll 4
    for (int c = 0; c < CM; c++){
        float v = x[c*NSPAT + s];
        sum += v; sq = fmaf(v, v, sq);
    }
    float mu  = sum * (1.f/CM);
    float var = sq  * (1.f/CM) - mu*mu;
    float rs  = rsqrtf(var + 1e-5f);
    int h = s >> 10, w = (s >> 5) & 31, d = s & 31;
    int b = (h>>3)*16 + (w>>3)*4 + (d>>3);
    int l = (h&7)*64 + (w&7)*8 + (d&7);
    int m = b*LSEQ + l;
    #pragma unroll 4
    for (int c = 0; c < CM; c++){
        float v = x[c*NSPAT + s];
        g_xn[m*CM + c] = (v - mu)*rs*lnw[c] + lnb[c];
    }
}

// ---------------- K2: in_proj GEMM  (32768x96)@(96x384)^T -> xz (m,e) ---------
__global__ void inproj_kernel(const float* __restrict__ W){
    __shared__ float As[48][64];
    __shared__ float Ws[48][64];
    int tid = threadIdx.x;            // 128
    int m0 = blockIdx.x * 64;         // 512 m-tiles
    int n0 = blockIdx.y * 64;         // 6 n-tiles
    float acc[4][8];
    #pragma unroll
    for (int i = 0; i < 4; i++)
        #pragma unroll
        for (int j = 0; j < 8; j++) acc[i][j] = 0.f;
    int lr = (tid & 15) * 4;
    int nr = (tid >> 4) * 8;
    for (int kk = 0; kk < 96; kk += 48){
        #pragma unroll
        for (int j = 0; j < 6; j++){
            int f = tid + j*128;              // 0..767
            int row = f / 12, kq = f % 12;
            float4 a = *(const float4*)&g_xn[(m0+row)*96 + kk + kq*4];
            As[kq*4+0][row] = a.x; As[kq*4+1][row] = a.y;
            As[kq*4+2][row] = a.z; As[kq*4+3][row] = a.w;
            float4 bvec = *(const float4*)&W[(n0+row)*96 + kk + kq*4];
            Ws[kq*4+0][row] = bvec.x; Ws[kq*4+1][row] = bvec.y;
            Ws[kq*4+2][row] = bvec.z; Ws[kq*4+3][row] = bvec.w;
        }
        __syncthreads();
        #pragma unroll
        for (int k = 0; k < 48; k++){
            float4 a  = *(const float4*)&As[k][lr];
            float4 b0 = *(const float4*)&Ws[k][nr];
            float4 b1 = *(const float4*)&Ws[k][nr+4];
            float av[4] = {a.x, a.y, a.z, a.w};
            float bv[8] = {b0.x, b0.y, b0.z, b0.w, b1.x, b1.y, b1.z, b1.w};
            #pragma unroll
            for (int i = 0; i < 4; i++)
                #pragma unroll
                for (int j = 0; j < 8; j++)
                    acc[i][j] = fmaf(av[i], bv[j], acc[i][j]);
        }
        __syncthreads();
    }
    #pragma unroll
    for (int i = 0; i < 4; i++){
        float4 c0 = make_float4(acc[i][0], acc[i][1], acc[i][2], acc[i][3]);
        float4 c1 = make_float4(acc[i][4], acc[i][5], acc[i][6], acc[i][7]);
        float* dst = &g_xz[(m0 + lr + i)*E2 + n0 + nr];
        *(float4*)dst       = c0;
        *(float4*)(dst + 4) = c1;
    }
}

// ---------------- K3: causal depthwise conv4 + SiLU (all 3 branches) ----------
__global__ void conv_kernel(const float* __restrict__ cw0, const float* __restrict__ cb0,
                            const float* __restrict__ cw1, const float* __restrict__ cb1,
                            const float* __restrict__ cw2, const float* __restrict__ cb2){
    int d  = threadIdx.x;             // 0..191
    int b  = blockIdx.y;              // 0..63
    int br = blockIdx.z;              // 0..2
    const float* cw = (br == 0) ? cw0 : (br == 1) ? cw1 : cw2;
    const float* cb = (br == 0) ? cb0 : (br == 1) ? cb1 : cb2;
    float w0 = cw[d*4+0], w1 = cw[d*4+1], w2 = cw[d*4+2], w3 = cw[d*4+3];
    float bias = cb[d];
    int t0 = blockIdx.x * 8;
    const float* xzb = g_xz + (size_t)b*LSEQ*E2 + d;
    float* ub = g_u[br] + (size_t)(b*LSEQ)*DI + d;
    for (int i = 0; i < 8; i++){
        int t = t0 + i;
        float acc = bias;
        float wv[4] = {w0, w1, w2, w3};
        #pragma unroll
        for (int k = 0; k < 4; k++){
            int tt = t - 3 + k;
            if (tt >= 0){
                int p = perm_idx(br, tt);
                acc = fmaf(wv[k], xzb[p*E2], acc);
            }
        }
        ub[t*DI] = siluf(acc);
    }
}

// ---------------- K4: x_dbl projection + delta/softplus + B/C split -----------
__global__ void xdbl_kernel(const float* __restrict__ xp0, const float* __restrict__ dw0, const float* __restrict__ db0,
                            const float* __restrict__ xp1, const float* __restrict__ dw1, const float* __restrict__ db1,
                            const float* __restrict__ xp2, const float* __restrict__ dw2, const float* __restrict__ db2){
    __shared__ float us[4][193];
    __shared__ float xd[4][38];
    int tid = threadIdx.x;            // 128
    int br  = blockIdx.z;
    const float* xpw = (br == 0) ? xp0 : (br == 1) ? xp1 : xp2;
    const float* dtw = (br == 0) ? dw0 : (br == 1) ? dw1 : dw2;
    const float* dtb = (br == 0) ? db0 : (br == 1) ? db1 : db2;
    int m0 = blockIdx.x * 4;          // 8192 blocks
    #pragma unroll
    for (int j = 0; j < 6; j++){
        int f = tid + j*128;          // 0..767
        int p = f / 192, k = f % 192;
        us[p][k] = g_u[br][(size_t)(m0+p)*DI + k];
    }
    __syncthreads();
    for (int o = tid; o < 152; o += 128){
        int p = o / 38, r = o % 38;
        float acc = 0.f;
        #pragma unroll 4
        for (int k = 0; k < 192; k++)
            acc = fmaf(us[p][k], xpw[r*192 + k], acc);
        xd[p][r] = acc;
        if (r >= 6 && r < 22)      g_Bm[br][(size_t)(m0+p)*DS + (r-6)]  = acc;
        else if (r >= 22)          g_Cm[br][(size_t)(m0+p)*DS + (r-22)] = acc;
    }
    __syncthreads();
    #pragma unroll
    for (int j = 0; j < 6; j++){
        int f = tid + j*128;
        int p = f / 192, d = f % 192;
        float acc = dtb[d];
        #pragma unroll
        for (int r = 0; r < 6; r++)
            acc = fmaf(xd[p][r], dtw[d*6 + r], acc);
        g_delta[br][(size_t)(m0+p)*DI + d] = softplusf(acc);
    }
}

// ---------------- K5: selective scan (all 3 branches, L sequential) -----------
__global__ void scan_kernel(const float* __restrict__ Al0, const float* __restrict__ Dp0,
                            const float* __restrict__ Al1, const float* __restrict__ Dp1,
                            const float* __restrict__ Al2, const float* __restrict__ Dp2){
    int d  = threadIdx.x;             // 0..191
    int b  = blockIdx.x;              // 0..63
    int br = blockIdx.y;              // 0..2
    const float* Alog = (br == 0) ? Al0 : (br == 1) ? Al1 : Al2;
    const float* Dp   = (br == 0) ? Dp0 : (br == 1) ? Dp1 : Dp2;
    float Ar[16];
    #pragma unroll
    for (int s = 0; s < 16; s++) Ar[s] = -__expf(Alog[d*16 + s]);
    float Dd = Dp[d];
    float h[16];
    #pragma unroll
    for (int s = 0; s < 16; s++) h[s] = 0.f;
    const float* dl = g_delta[br] + (size_t)(b*LSEQ)*DI + d;
    const float* ul = g_u[br]     + (size_t)(b*LSEQ)*DI + d;
    const float4* Bp = (const float4*)(g_Bm[br] + (size_t)(b*LSEQ)*DS);
    const float4* Cp = (const float4*)(g_Cm[br] + (size_t)(b*LSEQ)*DS);
    float* yb = g_y[br] + (size_t)(b*LSEQ)*DI + d;
    for (int t = 0; t < LSEQ; t++){
        float delta = dl[t*DI];
        float u     = ul[t*DI];
        float du    = delta * u;
        float4 B0 = Bp[t*4+0], B1 = Bp[t*4+1], B2 = Bp[t*4+2], B3 = Bp[t*4+3];
        float4 C0 = Cp[t*4+0], C1 = Cp[t*4+1], C2 = Cp[t*4+2], C3 = Cp[t*4+3];
        float Bv[16] = {B0.x,B0.y,B0.z,B0.w, B1.x,B1.y,B1.z,B1.w,
                        B2.x,B2.y,B2.z,B2.w, B3.x,B3.y,B3.z,B3.w};
        float Cv[16] = {C0.x,C0.y,C0.z,C0.w, C1.x,C1.y,C1.z,C1.w,
                        C2.x,C2.y,C2.z,C2.w, C3.x,C3.y,C3.z,C3.w};
        float y = 0.f;
        #pragma unroll
        for (int s = 0; s < 16; s++){
            float dA = __expf(delta * Ar[s]);
            h[s] = fmaf(h[s], dA, du * Bv[s]);
            y    = fmaf(h[s], Cv[s], y);
        }
        int lo = perm_idx(br, t);
        yb[lo*DI] = fmaf(Dd, u, y);
    }
}

// ------- K6: combine branches * silu(z), out_proj, window_reverse + residual --
__global__ void outproj_kernel(const float* __restrict__ W,
                               const float* __restrict__ x,
                               float* __restrict__ out){
    __shared__ float ss[16][193];
    int tid = threadIdx.x;            // 128
    int m0 = blockIdx.x * 16;         // 2048 blocks
    #pragma unroll
    for (int j = 0; j < 24; j++){
        int f = tid + j*128;          // 0..3071
        int p = f / 192, k = f % 192;
        size_t mi = (size_t)(m0+p)*DI + k;
        float ysum = g_y[0][mi] + g_y[1][mi] + g_y[2][mi];
        float z = g_xz[(size_t)(m0+p)*E2 + DI + k];
        ss[p][k] = ysum * siluf(z);
    }
    __syncthreads();
    int pg = (tid & 7) * 2;           // 0..14
    int c0 = (tid >> 3) * 6;          // 0..90
    float acc0[6], acc1[6];
    #pragma unroll
    for (int j = 0; j < 6; j++){ acc0[j] = 0.f; acc1[j] = 0.f; }
    #pragma unroll 4
    for (int k = 0; k < 192; k++){
        float s0 = ss[pg][k], s1 = ss[pg+1][k];
        #pragma unroll
        for (int j = 0; j < 6; j++){
            float wv = W[(c0+j)*192 + k];
            acc0[j] = fmaf(s0, wv, acc0[j]);
            acc1[j] = fmaf(s1, wv, acc1[j]);
        }
    }
    #pragma unroll
    for (int i = 0; i < 2; i++){
        int m = m0 + pg + i;
        int b = m >> 9, l = m & 511;
        int hb = b >> 4, wb = (b >> 2) & 3, db = b & 3;
        int lh = l >> 6, lw = (l >> 3) & 7, ld = l & 7;
        int sp = (hb*8+lh)*1024 + (wb*8+lw)*32 + (db*8+ld);
        #pragma unroll
        for (int j = 0; j < 6; j++){
            int oi = (c0+j)*NSPAT + sp;
            out[oi] = (i == 0 ? acc0[j] : acc1[j]) + x[oi];
        }
    }
}

// ---------------- K7/K8/K9: ECA (channel means -> conv3+sigmoid -> scale) -----
__global__ void mean_kernel(const float* __restrict__ out){
    __shared__ float red[256];
    int c = blockIdx.x;
    float s = 0.f;
    for (int i = threadIdx.x; i < NSPAT; i += 256) s += out[c*NSPAT + i];
    red[threadIdx.x] = s; __syncthreads();
    for (int st = 128; st > 0; st >>= 1){
        if (threadIdx.x < st) red[threadIdx.x] += red[threadIdx.x + st];
        __syncthreads();
    }
    if (threadIdx.x == 0) g_mean[c] = red[0] * (1.f/NSPAT);
}

__global__ void gate_kernel(const float* __restrict__ ew){
    int c = threadIdx.x;
    if (c < CM){
        float m0 = (c > 0)      ? g_mean[c-1] : 0.f;
        float m1 = g_mean[c];
        float m2 = (c < CM-1)   ? g_mean[c+1] : 0.f;
        float v = ew[0]*m0 + ew[1]*m1 + ew[2]*m2;
        g_gate[c] = 1.f / (1.f + __expf(-v));
    }
}

__global__ void scale_kernel(float* __restrict__ out){
    int i = blockIdx.x*256 + threadIdx.x;
    out[i] *= g_gate[i >> 15];    // 32768 spatial per channel
}

// -----------------------------------------------------------------------------
extern "C" void kernel_launch(void* const* d_in, const int* in_sizes, int n_in,
                              void* d_out, int out_size){
    const float* x   = (const float*)d_in[0];
    const float* lnw = (const float*)d_in[1];
    const float* lnb = (const float*)d_in[2];
    const float* ipw = (const float*)d_in[3];
    const float* opw = (const float*)d_in[4];
    // input order can be signature order (eca last) or dict order (eca at 5)
    int base, eca_idx;
    if (in_sizes[5] == 3) { eca_idx = 5;  base = 6; }
    else                  { base = 5;     eca_idx = 26; }
    const float* ecw = (const float*)d_in[eca_idx];
    const float *cw[3], *cb[3], *xp[3], *dw[3], *db[3], *Al[3], *Dp[3];
    for (int br = 0; br < 3; br++){
        const int o = base + 7*br;
        cw[br] = (const float*)d_in[o+0];
        cb[br] = (const float*)d_in[o+1];
        xp[br] = (const float*)d_in[o+2];
        dw[br] = (const float*)d_in[o+3];
        db[br] = (const float*)d_in[o+4];
        Al[br] = (const float*)d_in[o+5];
        Dp[br] = (const float*)d_in[o+6];
    }
    float* out = (float*)d_out;

    ln_kernel<<<NSPAT/256, 256>>>(x, lnw, lnb);
    { dim3 g(NPOS/64, E2/64); inproj_kernel<<<g, 128>>>(ipw); }
    { dim3 g(LSEQ/8, WNB, 3); conv_kernel<<<g, DI>>>(cw[0],cb[0],cw[1],cb[1],cw[2],cb[2]); }
    { dim3 g(NPOS/4, 1, 3);   xdbl_kernel<<<g, 128>>>(xp[0],dw[0],db[0],
                                                      xp[1],dw[1],db[1],
                                                      xp[2],dw[2],db[2]); }
    { dim3 g(WNB, 3);         scan_kernel<<<g, DI>>>(Al[0],Dp[0],Al[1],Dp[1],Al[2],Dp[2]); }
    outproj_kernel<<<NPOS/16, 128>>>(opw, x, out);
    mean_kernel<<<CM, 256>>>(out);
    gate_kernel<<<1, 128>>>(ecw);
    scale_kernel<<<(CM*NSPAT)/256, 256>>>(out);
    (void)n_in; (void)out_size;
}

// round 2
// speedup vs baseline: 5.9728x; 5.9728x over previous
#include <cuda_runtime.h>
#include <math.h>

#define WNB   64
#define LSEQ  512
#define CM    96
#define DI    192
#define DS    16
#define E2    384
#define NPOS  (WNB*LSEQ)   // 32768
#define NSPAT 32768

// ---------------- scratch ----------------------------------------------------
__device__ __align__(16) float g_xn[NPOS*CM];
__device__ __align__(16) float g_xz[NPOS*E2];
__device__ __align__(16) float g_u[3][NPOS*DI];
__device__ __align__(16) float g_delta[3][NPOS*DI];
__device__ __align__(16) float g_Bm[3][NPOS*DS];
__device__ __align__(16) float g_Cm[3][NPOS*DS];
__device__ __align__(16) float g_y[3][NPOS*DI];
__device__ float g_mean[CM];
__device__ float g_gate[CM];

__device__ __forceinline__ float siluf(float v){ return v / (1.f + __expf(-v)); }
__device__ __forceinline__ float softplusf(float v){ return v > 15.f ? v : log1pf(__expf(v)); }

__device__ __forceinline__ int perm_idx(int br, int t){
    if (br == 0) return t;
    if (br == 1) return 511 - t;
    return ((t & 7) << 6) + (t >> 3);
}

// ---------------- K1: layernorm + window gather (coalesced via smem tile) -----
__global__ void ln_kernel(const float* __restrict__ x,
                          const float* __restrict__ lnw,
                          const float* __restrict__ lnb){
    extern __shared__ float tile[];            // [96][129]
    __shared__ float s_mu[128], s_rs[128];
    __shared__ int   s_m[128];
    __shared__ float s_w[96], s_b[96];
    int tid = threadIdx.x;                     // 128
    int s0  = blockIdx.x * 128;
    if (tid < 96){ s_w[tid] = lnw[tid]; s_b[tid] = lnb[tid]; }
    int s = s0 + tid;
    float sum = 0.f, sq = 0.f;
    #pragma unroll 4
    for (int c = 0; c < 96; c++){
        float v = x[c*NSPAT + s];
        tile[c*129 + tid] = v;
        sum += v; sq = fmaf(v, v, sq);
    }
    float mu  = sum * (1.f/96);
    float var = sq  * (1.f/96) - mu*mu;
    s_mu[tid] = mu;
    s_rs[tid] = rsqrtf(var + 1e-5f);
    int h = s >> 10, w = (s >> 5) & 31, dd = s & 31;
    int b = (h>>3)*16 + (w>>3)*4 + (dd>>3);
    int l = (h&7)*64 + (w&7)*8 + (dd&7);
    s_m[tid] = b*LSEQ + l;
    __syncthreads();
    #pragma unroll 4
    for (int i = 0; i < 96; i++){
        int f = i*128 + tid;
        int c = f % 96, r = f / 96;
        float v = tile[c*129 + r];
        g_xn[s_m[r]*96 + c] = (v - s_mu[r])*s_rs[r]*s_w[c] + s_b[c];
    }
}

// ---------------- K2: in_proj GEMM (unchanged structure) ----------------------
__global__ void inproj_kernel(const float* __restrict__ W){
    __shared__ float As[48][64];
    __shared__ float Ws[48][64];
    int tid = threadIdx.x;            // 128
    int m0 = blockIdx.x * 64;
    int n0 = blockIdx.y * 64;
    float acc[4][8];
    #pragma unroll
    for (int i = 0; i < 4; i++)
        #pragma unroll
        for (int j = 0; j < 8; j++) acc[i][j] = 0.f;
    int lr = (tid & 15) * 4;
    int nr = (tid >> 4) * 8;
    for (int kk = 0; kk < 96; kk += 48){
        #pragma unroll
        for (int j = 0; j < 6; j++){
            int f = tid + j*128;
            int row = f / 12, kq = f % 12;
            float4 a = *(const float4*)&g_xn[(m0+row)*96 + kk + kq*4];
            As[kq*4+0][row] = a.x; As[kq*4+1][row] = a.y;
            As[kq*4+2][row] = a.z; As[kq*4+3][row] = a.w;
            float4 bvec = *(const float4*)&W[(n0+row)*96 + kk + kq*4];
            Ws[kq*4+0][row] = bvec.x; Ws[kq*4+1][row] = bvec.y;
            Ws[kq*4+2][row] = bvec.z; Ws[kq*4+3][row] = bvec.w;
        }
        __syncthreads();
        #pragma unroll
        for (int k = 0; k < 48; k++){
            float4 a  = *(const float4*)&As[k][lr];
            float4 b0 = *(const float4*)&Ws[k][nr];
            float4 b1 = *(const float4*)&Ws[k][nr+4];
            float av[4] = {a.x, a.y, a.z, a.w};
            float bv[8] = {b0.x, b0.y, b0.z, b0.w, b1.x, b1.y, b1.z, b1.w};
            #pragma unroll
            for (int i = 0; i < 4; i++)
                #pragma unroll
                for (int j = 0; j < 8; j++)
                    acc[i][j] = fmaf(av[i], bv[j], acc[i][j]);
        }
        __syncthreads();
    }
    #pragma unroll
    for (int i = 0; i < 4; i++){
        float4 c0 = make_float4(acc[i][0], acc[i][1], acc[i][2], acc[i][3]);
        float4 c1 = make_float4(acc[i][4], acc[i][5], acc[i][6], acc[i][7]);
        float* dst = &g_xz[(m0 + lr + i)*E2 + n0 + nr];
        *(float4*)dst       = c0;
        *(float4*)(dst + 4) = c1;
    }
}

// ---------------- K3: causal conv4 + SiLU, sliding window + deep prefetch -----
__global__ void conv_kernel(const float* __restrict__ cw0, const float* __restrict__ cb0,
                            const float* __restrict__ cw1, const float* __restrict__ cb1,
                            const float* __restrict__ cw2, const float* __restrict__ cb2){
    int d   = threadIdx.x;            // 0..191
    int tc  = blockIdx.x;             // 0..3  (t-chunk of 128)
    int b   = blockIdx.y;             // 0..63
    int br  = blockIdx.z;             // 0..2
    const float* cw = (br == 0) ? cw0 : (br == 1) ? cw1 : cw2;
    const float* cb = (br == 0) ? cb0 : (br == 1) ? cb1 : cb2;
    float w0 = cw[d*4+0], w1 = cw[d*4+1], w2 = cw[d*4+2], w3 = cw[d*4+3];
    float bias = cb[d];
    const float* xb = g_xz + (size_t)b*LSEQ*E2 + d;
    float* ub = g_u[br] + (size_t)(b*LSEQ)*DI + d;
    int t0 = tc*128;
    float x1 = 0.f, x2 = 0.f, x3 = 0.f;   // t-1, t-2, t-3
    if (t0 >= 1) x1 = xb[perm_idx(br, t0-1)*E2];
    if (t0 >= 2) x2 = xb[perm_idx(br, t0-2)*E2];
    if (t0 >= 3) x3 = xb[perm_idx(br, t0-3)*E2];
    float pf[8];
    #pragma unroll
    for (int j = 0; j < 8; j++) pf[j] = xb[perm_idx(br, t0+j)*E2];
    #pragma unroll 8
    for (int i = 0; i < 128; i++){
        int t = t0 + i;
        float xv = pf[i & 7];
        int tn = t + 8;
        if (tn < (tc+1)*128 + 8 && tn < LSEQ) pf[i & 7] = xb[perm_idx(br, tn)*E2];
        float acc = bias;
        acc = fmaf(w0, x3, acc);
        acc = fmaf(w1, x2, acc);
        acc = fmaf(w2, x1, acc);
        acc = fmaf(w3, xv, acc);
        ub[t*DI] = siluf(acc);
        x3 = x2; x2 = x1; x1 = xv;
    }
}

// ---------------- K4: x_dbl GEMM + delta + B/C (smem-tiled) -------------------
#define XT 4
__global__ void xdbl_kernel(const float* __restrict__ xp0, const float* __restrict__ dw0, const float* __restrict__ db0,
                            const float* __restrict__ xp1, const float* __restrict__ dw1, const float* __restrict__ db1,
                            const float* __restrict__ xp2, const float* __restrict__ dw2, const float* __restrict__ db2){
    extern __shared__ float sm[];
    float* ws_k = sm;                 // [192][44]
    float* us_k = ws_k + 192*44;      // [192][68]
    float* xds  = us_k + 192*68;      // [64][44]
    float* dtws = xds  + 64*44;       // [6][192]
    int tid = threadIdx.x;            // 192
    int br  = blockIdx.y;
    const float* xpw = (br == 0) ? xp0 : (br == 1) ? xp1 : xp2;
    const float* dtw = (br == 0) ? dw0 : (br == 1) ? dw1 : dw2;
    const float* dtb = (br == 0) ? db0 : (br == 1) ? db1 : db2;
    // zero pad columns r=38..43
    for (int f = tid; f < 192*6; f += 192){
        int k = f/6, r = 38 + f%6;
        ws_k[k*44 + r] = 0.f;
    }
    // stage weights transposed  [k][r]
    for (int f = tid; f < 38*48; f += 192){
        int r = f/48, k4 = f%48;
        float4 v = *(const float4*)&xpw[r*192 + 4*k4];
        ws_k[(4*k4+0)*44 + r] = v.x;
        ws_k[(4*k4+1)*44 + r] = v.y;
        ws_k[(4*k4+2)*44 + r] = v.z;
        ws_k[(4*k4+3)*44 + r] = v.w;
    }
    // stage dt weights transposed [r][d]
    for (int f = tid; f < 6*192; f += 192){
        int r = f/192, d = f%192;
        dtws[r*192 + d] = dtw[d*6 + r];
    }
    int mg = tid & 15;       // m group
    int rg = tid >> 4;       // r group (0..11, active<10)
    const float* gu = g_u[br];
    float* gB = g_Bm[br];
    float* gC = g_Cm[br];
    float* gD = g_delta[br];
    float dwr[6], db_;
    #pragma unroll
    for (int r = 0; r < 6; r++) dwr[r] = dtw[tid*6 + r];
    db_ = dtb[tid];
    for (int tt = 0; tt < XT; tt++){
        int m0 = (blockIdx.x*XT + tt)*64;
        __syncthreads();
        for (int f = tid; f < 64*48; f += 192){
            int m = f/48, k4 = f%48;
            float4 v = *(const float4*)&gu[(size_t)(m0+m)*192 + 4*k4];
            us_k[(4*k4+0)*68 + m] = v.x;
            us_k[(4*k4+1)*68 + m] = v.y;
            us_k[(4*k4+2)*68 + m] = v.z;
            us_k[(4*k4+3)*68 + m] = v.w;
        }
        __syncthreads();
        if (rg < 10){
            float acc[4][4];
            #pragma unroll
            for (int i = 0; i < 4; i++)
                #pragma unroll
                for (int j = 0; j < 4; j++) acc[i][j] = 0.f;
            #pragma unroll 4
            for (int k = 0; k < 192; k++){
                float4 a = *(const float4*)&us_k[k*68 + 4*mg];
                float4 w = *(const float4*)&ws_k[k*44 + 4*rg];
                float av[4] = {a.x, a.y, a.z, a.w};
                float wv[4] = {w.x, w.y, w.z, w.w};
                #pragma unroll
                for (int i = 0; i < 4; i++)
                    #pragma unroll
                    for (int j = 0; j < 4; j++)
                        acc[i][j] = fmaf(av[i], wv[j], acc[i][j]);
            }
            #pragma unroll
            for (int i = 0; i < 4; i++)
                #pragma unroll
                for (int j = 0; j < 4; j++)
                    xds[(4*mg+i)*44 + 4*rg+j] = acc[i][j];
        }
        __syncthreads();
        // scatter B, C  (xd cols 6..21 -> B, 22..37 -> C)
        for (int f = tid; f < 64*32; f += 192){
            int m = f >> 5, j = f & 31;
            float v = xds[m*44 + 6 + j];
            if (j < 16) gB[(size_t)(m0+m)*DS + j]      = v;
            else        gC[(size_t)(m0+m)*DS + (j-16)] = v;
        }
        // delta = softplus(dt @ dtw^T + dtb)
        #pragma unroll 4
        for (int i = 0; i < 64; i++){
            float acc = db_;
            #pragma unroll
            for (int r = 0; r < 6; r++)
                acc = fmaf(xds[i*44 + r], dwr[r], acc);
            gD[(size_t)(m0+i)*DI + tid] = softplusf(acc);
        }
    }
}

// ---------------- K5: selective scan (chunked smem + register prefetch) -------
__global__ void scan_kernel(const float* __restrict__ Al0, const float* __restrict__ Dp0,
                            const float* __restrict__ Al1, const float* __restrict__ Dp1,
                            const float* __restrict__ Al2, const float* __restrict__ Dp2){
    __shared__ float sd[16*96];
    __shared__ float su[16*96];
    __shared__ __align__(16) float sB[16*16];
    __shared__ __align__(16) float sC[16*16];
    int tid  = threadIdx.x;           // 0..95
    int b    = blockIdx.x;            // 0..63
    int half = blockIdx.y;            // 0..1
    int br   = blockIdx.z;            // 0..2
    int d    = half*96 + tid;
    const float* Alog = (br == 0) ? Al0 : (br == 1) ? Al1 : Al2;
    const float* Dp   = (br == 0) ? Dp0 : (br == 1) ? Dp1 : Dp2;
    float Ar[16];
    #pragma unroll
    for (int s = 0; s < 16; s++) Ar[s] = -__expf(Alog[d*16 + s]);
    float Dd = Dp[d];
    float h[16];
    #pragma unroll
    for (int s = 0; s < 16; s++) h[s] = 0.f;
    const float* gdp = g_delta[br] + (size_t)(b*LSEQ)*DI + d;
    const float* gup = g_u[br]     + (size_t)(b*LSEQ)*DI + d;
    const float* gBp = g_Bm[br]    + (size_t)(b*LSEQ)*DS;
    const float* gCp = g_Cm[br]    + (size_t)(b*LSEQ)*DS;
    float* yb = g_y[br] + (size_t)(b*LSEQ)*DI + d;
    float pd[16], pu[16], pb[3], pc[3];
    // preload chunk 0
    #pragma unroll
    for (int i = 0; i < 16; i++){ pd[i] = gdp[i*DI]; pu[i] = gup[i*DI]; }
    #pragma unroll
    for (int i = 0; i < 3; i++){
        int idx = i*96 + tid;
        pb[i] = (idx < 256) ? gBp[idx] : 0.f;
        pc[i] = (idx < 256) ? gCp[idx] : 0.f;
    }
    for (int c = 0; c < 32; c++){
        #pragma unroll
        for (int i = 0; i < 16; i++){ sd[i*96+tid] = pd[i]; su[i*96+tid] = pu[i]; }
        #pragma unroll
        for (int i = 0; i < 3; i++){
            int idx = i*96 + tid;
            if (idx < 256){ sB[idx] = pb[i]; sC[idx] = pc[i]; }
        }
        __syncthreads();
        if (c + 1 < 32){
            size_t ofs = (size_t)(c+1)*16*DI;
            #pragma unroll
            for (int i = 0; i < 16; i++){ pd[i] = gdp[ofs + i*DI]; pu[i] = gup[ofs + i*DI]; }
            int ofb = (c+1)*256;
            #pragma unroll
            for (int i = 0; i < 3; i++){
                int idx = i*96 + tid;
                if (idx < 256){ pb[i] = gBp[ofb + idx]; pc[i] = gCp[ofb + idx]; }
            }
        }
        for (int t2 = 0; t2 < 16; t2++){
            float delta = sd[t2*96 + tid];
            float u     = su[t2*96 + tid];
            float du    = delta * u;
            const float4* B4 = (const float4*)(sB + t2*16);
            const float4* C4 = (const float4*)(sC + t2*16);
            float4 B0 = B4[0], B1 = B4[1], B2 = B4[2], B3 = B4[3];
            float4 C0 = C4[0], C1 = C4[1], C2 = C4[2], C3 = C4[3];
            float Bv[16] = {B0.x,B0.y,B0.z,B0.w, B1.x,B1.y,B1.z,B1.w,
                            B2.x,B2.y,B2.z,B2.w, B3.x,B3.y,B3.z,B3.w};
            float Cv[16] = {C0.x,C0.y,C0.z,C0.w, C1.x,C1.y,C1.z,C1.w,
                            C2.x,C2.y,C2.z,C2.w, C3.x,C3.y,C3.z,C3.w};
            float y = 0.f;
            #pragma unroll
            for (int s = 0; s < 16; s++){
                float dA = __expf(delta * Ar[s]);
                h[s] = fmaf(h[s], dA, du * Bv[s]);
                y    = fmaf(h[s], Cv[s], y);
            }
            int t = c*16 + t2;
            yb[perm_idx(br, t)*DI] = fmaf(Dd, u, y);
        }
        __syncthreads();
    }
}

// ---------------- K6: combine*silu(z) + out_proj GEMM + reverse + residual ----
__global__ void outproj_kernel(const float* __restrict__ W,
                               const float* __restrict__ x,
                               float* __restrict__ out){
    __shared__ float As[32*68];       // [k][m]
    __shared__ float Ws2[32*100];     // [k][c]
    __shared__ float Cs[64*97];       // [m][c]
    int tid = threadIdx.x;            // 256
    int m0 = blockIdx.x * 64;
    int mg = tid & 15;
    int ng = tid >> 4;                // 0..15
    float acc[4][6];
    #pragma unroll
    for (int i = 0; i < 4; i++)
        #pragma unroll
        for (int j = 0; j < 6; j++) acc[i][j] = 0.f;
    for (int kk = 0; kk < 192; kk += 32){
        __syncthreads();
        for (int f = tid; f < 512; f += 256){
            int m = f >> 3, k4 = f & 7;
            size_t mi = (size_t)(m0+m)*DI + kk + 4*k4;
            float4 y0 = *(const float4*)&g_y[0][mi];
            float4 y1 = *(const float4*)&g_y[1][mi];
            float4 y2 = *(const float4*)&g_y[2][mi];
            float4 z  = *(const float4*)&g_xz[(size_t)(m0+m)*E2 + DI + kk + 4*k4];
            As[(4*k4+0)*68 + m] = (y0.x+y1.x+y2.x)*siluf(z.x);
            As[(4*k4+1)*68 + m] = (y0.y+y1.y+y2.y)*siluf(z.y);
            As[(4*k4+2)*68 + m] = (y0.z+y1.z+y2.z)*siluf(z.z);
            As[(4*k4+3)*68 + m] = (y0.w+y1.w+y2.w)*siluf(z.w);
        }
        for (int f = tid; f < 768; f += 256){
            int cc = f >> 3, k4 = f & 7;
            float4 wv = *(const float4*)&W[cc*DI + kk + 4*k4];
            Ws2[(4*k4+0)*100 + cc] = wv.x;
            Ws2[(4*k4+1)*100 + cc] = wv.y;
            Ws2[(4*k4+2)*100 + cc] = wv.z;
            Ws2[(4*k4+3)*100 + cc] = wv.w;
        }
        __syncthreads();
        #pragma unroll 4
        for (int k = 0; k < 32; k++){
            float4 a = *(const float4*)&As[k*68 + 4*mg];
            float av[4] = {a.x, a.y, a.z, a.w};
            float wv[6];
            #pragma unroll
            for (int j = 0; j < 6; j++) wv[j] = Ws2[k*100 + 6*ng + j];
            #pragma unroll
            for (int i = 0; i < 4; i++)
                #pragma unroll
                for (int j = 0; j < 6; j++)
                    acc[i][j] = fmaf(av[i], wv[j], acc[i][j]);
        }
    }
    __syncthreads();
    #pragma unroll
    for (int i = 0; i < 4; i++)
        #pragma unroll
        for (int j = 0; j < 6; j++)
            Cs[(4*mg+i)*97 + 6*ng+j] = acc[i][j];
    __syncthreads();
    for (int f = tid; f < 64*96; f += 256){
        int cc = f >> 6, m = f & 63;
        int M = m0 + m;
        int b = M >> 9, l = M & 511;
        int hb = b >> 4, wb = (b >> 2) & 3, db = b & 3;
        int lh = l >> 6, lw = (l >> 3) & 7, ld = l & 7;
        int sp = (hb*8+lh)*1024 + (wb*8+lw)*32 + (db*8+ld);
        int oi = cc*NSPAT + sp;
        out[oi] = Cs[m*97 + cc] + x[oi];
    }
}

// ---------------- K7/K8/K9: ECA ----------------------------------------------
__global__ void mean_kernel(const float* __restrict__ out){
    __shared__ float red[256];
    int c = blockIdx.x;
    float s = 0.f;
    for (int i = threadIdx.x; i < NSPAT; i += 256) s += out[c*NSPAT + i];
    red[threadIdx.x] = s; __syncthreads();
    for (int st = 128; st > 0; st >>= 1){
        if (threadIdx.x < st) red[threadIdx.x] += red[threadIdx.x + st];
        __syncthreads();
    }
    if (threadIdx.x == 0) g_mean[c] = red[0] * (1.f/NSPAT);
}

__global__ void gate_kernel(const float* __restrict__ ew){
    int c = threadIdx.x;
    if (c < CM){
        float m0 = (c > 0)    ? g_mean[c-1] : 0.f;
        float m1 = g_mean[c];
        float m2 = (c < CM-1) ? g_mean[c+1] : 0.f;
        float v = ew[0]*m0 + ew[1]*m1 + ew[2]*m2;
        g_gate[c] = 1.f / (1.f + __expf(-v));
    }
}

__global__ void scale_kernel(float* __restrict__ out){
    int i = blockIdx.x*256 + threadIdx.x;
    out[i] *= g_gate[i >> 15];
}

// -----------------------------------------------------------------------------
extern "C" void kernel_launch(void* const* d_in, const int* in_sizes, int n_in,
                              void* d_out, int out_size){
    const float* x   = (const float*)d_in[0];
    const float* lnw = (const float*)d_in[1];
    const float* lnb = (const float*)d_in[2];
    const float* ipw = (const float*)d_in[3];
    const float* opw = (const float*)d_in[4];
    int base, eca_idx;
    if (in_sizes[5] == 3) { eca_idx = 5;  base = 6; }
    else                  { base = 5;     eca_idx = 26; }
    const float* ecw = (const float*)d_in[eca_idx];
    const float *cw[3], *cb[3], *xp[3], *dw[3], *db[3], *Al[3], *Dp[3];
    for (int br = 0; br < 3; br++){
        const int o = base + 7*br;
        cw[br] = (const float*)d_in[o+0];
        cb[br] = (const float*)d_in[o+1];
        xp[br] = (const float*)d_in[o+2];
        dw[br] = (const float*)d_in[o+3];
        db[br] = (const float*)d_in[o+4];
        Al[br] = (const float*)d_in[o+5];
        Dp[br] = (const float*)d_in[o+6];
    }
    float* out = (float*)d_out;

    cudaFuncSetAttribute(ln_kernel,   cudaFuncAttributeMaxDynamicSharedMemorySize, 96*129*4);
    cudaFuncSetAttribute(xdbl_kernel, cudaFuncAttributeMaxDynamicSharedMemorySize,
                         (192*44 + 192*68 + 64*44 + 6*192)*4);

    ln_kernel<<<NSPAT/128, 128, 96*129*4>>>(x, lnw, lnb);
    { dim3 g(NPOS/64, E2/64); inproj_kernel<<<g, 128>>>(ipw); }
    { dim3 g(4, WNB, 3); conv_kernel<<<g, DI>>>(cw[0],cb[0],cw[1],cb[1],cw[2],cb[2]); }
    { dim3 g(NPOS/(64*XT), 3);
      xdbl_kernel<<<g, 192, (192*44 + 192*68 + 64*44 + 6*192)*4>>>(
          xp[0],dw[0],db[0], xp[1],dw[1],db[1], xp[2],dw[2],db[2]); }
    { dim3 g(WNB, 2, 3); scan_kernel<<<g, 96>>>(Al[0],Dp[0],Al[1],Dp[1],Al[2],Dp[2]); }
    outproj_kernel<<<NPOS/64, 256>>>(opw, x, out);
    mean_kernel<<<CM, 256>>>(out);
    gate_kernel<<<1, 128>>>(ecw);
    scale_kernel<<<(CM*NSPAT)/256, 256>>>(out);
    (void)n_in; (void)out_size;
}

// round 3
// speedup vs baseline: 7.9449x; 1.3302x over previous
#include <cuda_runtime.h>
#include <math.h>

#define WNB   64
#define LSEQ  512
#define CM    96
#define DI    192
#define DS    16
#define E2    384
#define NPOS  (WNB*LSEQ)   // 32768
#define NSPAT 32768

// ---------------- scratch ----------------------------------------------------
__device__ __align__(16) float g_xn[NPOS*CM];
__device__ __align__(16) float g_xz[NPOS*E2];
__device__ __align__(16) float g_u[3][NPOS*DI];
__device__ __align__(16) float g_delta[3][NPOS*DI];
__device__ __align__(16) float g_Bm[3][NPOS*DS];
__device__ __align__(16) float g_Cm[3][NPOS*DS];
__device__ __align__(16) float g_y[3][NPOS*DI];
__device__ float g_mean[CM];
__device__ float g_gate[CM];

__device__ __forceinline__ float siluf(float v){ return v / (1.f + __expf(-v)); }
__device__ __forceinline__ float softplusf(float v){ return v > 15.f ? v : __logf(1.f + __expf(v)); }

typedef unsigned long long ull;
__device__ __forceinline__ ull fma2(ull a, ull b, ull c){
    ull d; asm("fma.rn.f32x2 %0, %1, %2, %3;" : "=l"(d) : "l"(a), "l"(b), "l"(c)); return d;
}
__device__ __forceinline__ ull mul2(ull a, ull b){
    ull d; asm("mul.rn.f32x2 %0, %1, %2;" : "=l"(d) : "l"(a), "l"(b)); return d;
}
__device__ __forceinline__ ull pack2(float lo, float hi){
    ull d; asm("mov.b64 %0, {%1, %2};" : "=l"(d) : "f"(lo), "f"(hi)); return d;
}
__device__ __forceinline__ float2 unpack2(ull v){
    float2 r; asm("mov.b64 {%0, %1}, %2;" : "=f"(r.x), "=f"(r.y) : "l"(v)); return r;
}

__device__ __forceinline__ int perm_idx(int br, int t){
    if (br == 0) return t;
    if (br == 1) return 511 - t;
    return ((t & 7) << 6) + (t >> 3);
}

// ---------------- K1: layernorm + window gather -------------------------------
__global__ void ln_kernel(const float* __restrict__ x,
                          const float* __restrict__ lnw,
                          const float* __restrict__ lnb){
    extern __shared__ float tile[];            // [96][129]
    __shared__ float s_mu[128], s_rs[128];
    __shared__ int   s_m[128];
    __shared__ float s_w[96], s_b[96];
    int tid = threadIdx.x;                     // 128
    int s0  = blockIdx.x * 128;
    if (tid < 96){ s_w[tid] = lnw[tid]; s_b[tid] = lnb[tid]; }
    int s = s0 + tid;
    float sum = 0.f, sq = 0.f;
    #pragma unroll 4
    for (int c = 0; c < 96; c++){
        float v = x[c*NSPAT + s];
        tile[c*129 + tid] = v;
        sum += v; sq = fmaf(v, v, sq);
    }
    float mu  = sum * (1.f/96);
    float var = sq  * (1.f/96) - mu*mu;
    s_mu[tid] = mu;
    s_rs[tid] = rsqrtf(var + 1e-5f);
    int h = s >> 10, w = (s >> 5) & 31, dd = s & 31;
    int b = (h>>3)*16 + (w>>3)*4 + (dd>>3);
    int l = (h&7)*64 + (w&7)*8 + (dd&7);
    s_m[tid] = b*LSEQ + l;
    __syncthreads();
    #pragma unroll 4
    for (int i = 0; i < 96; i++){
        int f = i*128 + tid;
        int c = f % 96, r = f / 96;
        float v = tile[c*129 + r];
        g_xn[s_m[r]*96 + c] = (v - s_mu[r])*s_rs[r]*s_w[c] + s_b[c];
    }
}

// ---------------- K2: in_proj GEMM --------------------------------------------
__global__ void inproj_kernel(const float* __restrict__ W){
    __shared__ float As[48][64];
    __shared__ float Ws[48][64];
    int tid = threadIdx.x;            // 128
    int m0 = blockIdx.x * 64;
    int n0 = blockIdx.y * 64;
    float acc[4][8];
    #pragma unroll
    for (int i = 0; i < 4; i++)
        #pragma unroll
        for (int j = 0; j < 8; j++) acc[i][j] = 0.f;
    int lr = (tid & 15) * 4;
    int nr = (tid >> 4) * 8;
    for (int kk = 0; kk < 96; kk += 48){
        #pragma unroll
        for (int j = 0; j < 6; j++){
            int f = tid + j*128;
            int row = f / 12, kq = f % 12;
            float4 a = *(const float4*)&g_xn[(m0+row)*96 + kk + kq*4];
            As[kq*4+0][row] = a.x; As[kq*4+1][row] = a.y;
            As[kq*4+2][row] = a.z; As[kq*4+3][row] = a.w;
            float4 bvec = *(const float4*)&W[(n0+row)*96 + kk + kq*4];
            Ws[kq*4+0][row] = bvec.x; Ws[kq*4+1][row] = bvec.y;
            Ws[kq*4+2][row] = bvec.z; Ws[kq*4+3][row] = bvec.w;
        }
        __syncthreads();
        #pragma unroll
        for (int k = 0; k < 48; k++){
            float4 a  = *(const float4*)&As[k][lr];
            float4 b0 = *(const float4*)&Ws[k][nr];
            float4 b1 = *(const float4*)&Ws[k][nr+4];
            float av[4] = {a.x, a.y, a.z, a.w};
            float bv[8] = {b0.x, b0.y, b0.z, b0.w, b1.x, b1.y, b1.z, b1.w};
            #pragma unroll
            for (int i = 0; i < 4; i++)
                #pragma unroll
                for (int j = 0; j < 8; j++)
                    acc[i][j] = fmaf(av[i], bv[j], acc[i][j]);
        }
        __syncthreads();
    }
    #pragma unroll
    for (int i = 0; i < 4; i++){
        float4 c0 = make_float4(acc[i][0], acc[i][1], acc[i][2], acc[i][3]);
        float4 c1 = make_float4(acc[i][4], acc[i][5], acc[i][6], acc[i][7]);
        float* dst = &g_xz[(m0 + lr + i)*E2 + n0 + nr];
        *(float4*)dst       = c0;
        *(float4*)(dst + 4) = c1;
    }
}

// ---------------- K3: causal conv4 + SiLU -------------------------------------
__global__ void conv_kernel(const float* __restrict__ cw0, const float* __restrict__ cb0,
                            const float* __restrict__ cw1, const float* __restrict__ cb1,
                            const float* __restrict__ cw2, const float* __restrict__ cb2){
    int d   = threadIdx.x;            // 0..191
    int tc  = blockIdx.x;             // 0..3
    int b   = blockIdx.y;             // 0..63
    int br  = blockIdx.z;             // 0..2
    const float* cw = (br == 0) ? cw0 : (br == 1) ? cw1 : cw2;
    const float* cb = (br == 0) ? cb0 : (br == 1) ? cb1 : cb2;
    float w0 = cw[d*4+0], w1 = cw[d*4+1], w2 = cw[d*4+2], w3 = cw[d*4+3];
    float bias = cb[d];
    const float* xb = g_xz + (size_t)b*LSEQ*E2 + d;
    float* ub = g_u[br] + (size_t)(b*LSEQ)*DI + d;
    int t0 = tc*128;
    float x1 = 0.f, x2 = 0.f, x3 = 0.f;
    if (t0 >= 1) x1 = xb[perm_idx(br, t0-1)*E2];
    if (t0 >= 2) x2 = xb[perm_idx(br, t0-2)*E2];
    if (t0 >= 3) x3 = xb[perm_idx(br, t0-3)*E2];
    float pf[8];
    #pragma unroll
    for (int j = 0; j < 8; j++) pf[j] = xb[perm_idx(br, t0+j)*E2];
    #pragma unroll 8
    for (int i = 0; i < 128; i++){
        int t = t0 + i;
        float xv = pf[i & 7];
        int tn = t + 8;
        if (tn < (tc+1)*128 + 8 && tn < LSEQ) pf[i & 7] = xb[perm_idx(br, tn)*E2];
        float acc = bias;
        acc = fmaf(w0, x3, acc);
        acc = fmaf(w1, x2, acc);
        acc = fmaf(w2, x1, acc);
        acc = fmaf(w3, xv, acc);
        ub[t*DI] = siluf(acc);
        x3 = x2; x2 = x1; x1 = xv;
    }
}

// ---------------- K4: x_dbl GEMM + delta + B/C --------------------------------
// block: 256 thr, tile M=128, N=40(38), K=192 (chunks of 64)
// smem: ws[192][45] (34.6KB) | us[64][132] (33.8KB, overlaid by xds[128][45])
#define XDBL_SMEM ((192*45 + 64*132)*4)
__global__ void xdbl_kernel(const float* __restrict__ xp0, const float* __restrict__ dw0, const float* __restrict__ db0,
                            const float* __restrict__ xp1, const float* __restrict__ dw1, const float* __restrict__ db1,
                            const float* __restrict__ xp2, const float* __restrict__ dw2, const float* __restrict__ db2){
    extern __shared__ float sm[];
    float* ws = sm;                 // [192][45]
    float* us = sm + 192*45;        // [64][132]  (later: xds [128][45])
    float* xds = us;
    int tid = threadIdx.x;          // 256
    int br  = blockIdx.y;
    int m0  = blockIdx.x * 128;
    const float* xpw = (br == 0) ? xp0 : (br == 1) ? xp1 : xp2;
    const float* dtw = (br == 0) ? dw0 : (br == 1) ? dw1 : dw2;
    const float* dtb = (br == 0) ? db0 : (br == 1) ? db1 : db2;
    const float* gu = g_u[br];
    // stage weights transposed [k][r]
    for (int f = tid; f < 38*48; f += 256){
        int r = f/48, k4 = f%48;
        float4 v = *(const float4*)&xpw[r*192 + 4*k4];
        ws[(4*k4+0)*45 + r] = v.x;
        ws[(4*k4+1)*45 + r] = v.y;
        ws[(4*k4+2)*45 + r] = v.z;
        ws[(4*k4+3)*45 + r] = v.w;
    }
    int mg = tid & 31;      // m group: 4 rows
    int rg = tid >> 5;      // r group: 5 cols (0..7)
    float acc[4][5];
    #pragma unroll
    for (int i = 0; i < 4; i++)
        #pragma unroll
        for (int j = 0; j < 5; j++) acc[i][j] = 0.f;
    for (int kk = 0; kk < 192; kk += 64){
        __syncthreads();
        // stage u chunk transposed [k][m]
        for (int f = tid; f < 2048; f += 256){
            int c = f & 15, m = f >> 4;
            float4 v = *(const float4*)&gu[(size_t)(m0+m)*192 + kk + 4*c];
            us[(4*c+0)*132 + m] = v.x;
            us[(4*c+1)*132 + m] = v.y;
            us[(4*c+2)*132 + m] = v.z;
            us[(4*c+3)*132 + m] = v.w;
        }
        __syncthreads();
        #pragma unroll 4
        for (int k = 0; k < 64; k++){
            float4 a = *(const float4*)&us[k*132 + 4*mg];
            const float* wr = &ws[(kk+k)*45 + 5*rg];
            float av[4] = {a.x, a.y, a.z, a.w};
            float wv[5] = {wr[0], wr[1], wr[2], wr[3], wr[4]};
            #pragma unroll
            for (int i = 0; i < 4; i++)
                #pragma unroll
                for (int j = 0; j < 5; j++)
                    acc[i][j] = fmaf(av[i], wv[j], acc[i][j]);
        }
    }
    __syncthreads();
    #pragma unroll
    for (int i = 0; i < 4; i++)
        #pragma unroll
        for (int j = 0; j < 5; j++)
            xds[(4*mg+i)*45 + 5*rg+j] = acc[i][j];
    __syncthreads();
    // scatter B, C
    float* gB = g_Bm[br];
    float* gC = g_Cm[br];
    for (int f = tid; f < 128*32; f += 256){
        int m = f >> 5, j = f & 31;
        float v = xds[m*45 + 6 + j];
        if (j < 16) gB[(size_t)(m0+m)*DS + j]      = v;
        else        gC[(size_t)(m0+m)*DS + (j-16)] = v;
    }
    // delta
    if (tid < 192){
        float dwr[6];
        #pragma unroll
        for (int r = 0; r < 6; r++) dwr[r] = dtw[tid*6 + r];
        float db_ = dtb[tid];
        float* gD = g_delta[br];
        #pragma unroll 4
        for (int m = 0; m < 128; m++){
            float acc2 = db_;
            #pragma unroll
            for (int r = 0; r < 6; r++)
                acc2 = fmaf(xds[m*45 + r], dwr[r], acc2);
            gD[(size_t)(m0+m)*DI + tid] = softplusf(acc2);
        }
    }
}

// ---------------- K5: selective scan (f32x2 + power-tree exp) -----------------
__global__ void scan_kernel(const float* __restrict__ Al0, const float* __restrict__ Dp0,
                            const float* __restrict__ Al1, const float* __restrict__ Dp1,
                            const float* __restrict__ Al2, const float* __restrict__ Dp2){
    __shared__ float sd[16*96];
    __shared__ float su[16*96];
    __shared__ __align__(16) float sB[16*16];
    __shared__ __align__(16) float sC[16*16];
    int tid  = threadIdx.x;           // 0..95
    int b    = blockIdx.x;            // 0..63
    int half = blockIdx.y;            // 0..1
    int br   = blockIdx.z;            // 0..2
    int d    = half*96 + tid;
    const float* Alog = (br == 0) ? Al0 : (br == 1) ? Al1 : Al2;
    const float* Dp   = (br == 0) ? Dp0 : (br == 1) ? Dp1 : Dp2;
    float Ar[16];
    #pragma unroll
    for (int s = 0; s < 16; s++) Ar[s] = -__expf(Alog[d*16 + s]);
    bool fast = true;
    #pragma unroll
    for (int s = 0; s < 16; s++)
        fast = fast && (fabsf(Ar[s] + (float)(s+1)) < 1e-3f*(float)(s+1));
    float Ar0 = Ar[0];
    float Dd = Dp[d];
    ull h2[8];
    #pragma unroll
    for (int s = 0; s < 8; s++) h2[s] = 0ull;
    float hs[16];
    #pragma unroll
    for (int s = 0; s < 16; s++) hs[s] = 0.f;
    const float* gdp = g_delta[br] + (size_t)(b*LSEQ)*DI + d;
    const float* gup = g_u[br]     + (size_t)(b*LSEQ)*DI + d;
    const float* gBp = g_Bm[br]    + (size_t)(b*LSEQ)*DS;
    const float* gCp = g_Cm[br]    + (size_t)(b*LSEQ)*DS;
    float* yb = g_y[br] + (size_t)(b*LSEQ)*DI + d;
    float pd[16], pu[16], pb[3], pc[3];
    #pragma unroll
    for (int i = 0; i < 16; i++){ pd[i] = gdp[i*DI]; pu[i] = gup[i*DI]; }
    #pragma unroll
    for (int i = 0; i < 3; i++){
        int idx = i*96 + tid;
        pb[i] = (idx < 256) ? gBp[idx] : 0.f;
        pc[i] = (idx < 256) ? gCp[idx] : 0.f;
    }
    for (int c = 0; c < 32; c++){
        #pragma unroll
        for (int i = 0; i < 16; i++){ sd[i*96+tid] = pd[i]; su[i*96+tid] = pu[i]; }
        #pragma unroll
        for (int i = 0; i < 3; i++){
            int idx = i*96 + tid;
            if (idx < 256){ sB[idx] = pb[i]; sC[idx] = pc[i]; }
        }
        __syncthreads();
        if (c + 1 < 32){
            size_t ofs = (size_t)(c+1)*16*DI;
            #pragma unroll
            for (int i = 0; i < 16; i++){ pd[i] = gdp[ofs + i*DI]; pu[i] = gup[ofs + i*DI]; }
            int ofb = (c+1)*256;
            #pragma unroll
            for (int i = 0; i < 3; i++){
                int idx = i*96 + tid;
                if (idx < 256){ pb[i] = gBp[ofb + idx]; pc[i] = gCp[ofb + idx]; }
            }
        }
        if (fast){
            for (int t2 = 0; t2 < 16; t2++){
                float delta = sd[t2*96 + tid];
                float u     = su[t2*96 + tid];
                float du    = delta * u;
                float q  = __expf(delta * Ar0);
                float q2 = q*q;
                ull v0 = pack2(q, q2);
                ull s2 = pack2(q2, q2);
                ull v1 = mul2(v0, s2);
                float q4 = unpack2(v1).y;
                ull s4 = pack2(q4, q4);
                ull v2 = mul2(v0, s4);
                ull v3 = mul2(v1, s4);
                float q8 = unpack2(v3).y;
                ull s8 = pack2(q8, q8);
                ull pw[8] = {v0, v1, v2, v3,
                             mul2(v0, s8), mul2(v1, s8), mul2(v2, s8), mul2(v3, s8)};
                ull du2 = pack2(du, du);
                const ulonglong2* B2 = (const ulonglong2*)(sB + t2*16);
                const ulonglong2* C2 = (const ulonglong2*)(sC + t2*16);
                ull y2 = 0ull;
                #pragma unroll
                for (int i = 0; i < 4; i++){
                    ulonglong2 Bv = B2[i];
                    ulonglong2 Cv = C2[i];
                    h2[2*i]   = fma2(h2[2*i],   pw[2*i],   mul2(Bv.x, du2));
                    y2 = fma2(h2[2*i], Cv.x, y2);
                    h2[2*i+1] = fma2(h2[2*i+1], pw[2*i+1], mul2(Bv.y, du2));
                    y2 = fma2(h2[2*i+1], Cv.y, y2);
                }
                float2 yy = unpack2(y2);
                int t = c*16 + t2;
                yb[perm_idx(br, t)*DI] = fmaf(Dd, u, yy.x + yy.y);
            }
        } else {
            for (int t2 = 0; t2 < 16; t2++){
                float delta = sd[t2*96 + tid];
                float u     = su[t2*96 + tid];
                float du    = delta * u;
                float y = 0.f;
                #pragma unroll
                for (int s = 0; s < 16; s++){
                    float dA = __expf(delta * Ar[s]);
                    hs[s] = fmaf(hs[s], dA, du * sB[t2*16 + s]);
                    y     = fmaf(hs[s], sC[t2*16 + s], y);
                }
                int t = c*16 + t2;
                yb[perm_idx(br, t)*DI] = fmaf(Dd, u, y);
            }
        }
        __syncthreads();
    }
}

// ---------------- K6: combine*silu(z) + out_proj + reverse + residual ---------
__global__ void outproj_kernel(const float* __restrict__ W,
                               const float* __restrict__ x,
                               float* __restrict__ out){
    __shared__ float As[32*68];
    __shared__ float Ws2[32*100];
    __shared__ float Cs[64*97];
    int tid = threadIdx.x;            // 256
    int m0 = blockIdx.x * 64;
    int mg = tid & 15;
    int ng = tid >> 4;
    float acc[4][6];
    #pragma unroll
    for (int i = 0; i < 4; i++)
        #pragma unroll
        for (int j = 0; j < 6; j++) acc[i][j] = 0.f;
    for (int kk = 0; kk < 192; kk += 32){
        __syncthreads();
        for (int f = tid; f < 512; f += 256){
            int m = f >> 3, k4 = f & 7;
            size_t mi = (size_t)(m0+m)*DI + kk + 4*k4;
            float4 y0 = *(const float4*)&g_y[0][mi];
            float4 y1 = *(const float4*)&g_y[1][mi];
            float4 y2 = *(const float4*)&g_y[2][mi];
            float4 z  = *(const float4*)&g_xz[(size_t)(m0+m)*E2 + DI + kk + 4*k4];
            As[(4*k4+0)*68 + m] = (y0.x+y1.x+y2.x)*siluf(z.x);
            As[(4*k4+1)*68 + m] = (y0.y+y1.y+y2.y)*siluf(z.y);
            As[(4*k4+2)*68 + m] = (y0.z+y1.z+y2.z)*siluf(z.z);
            As[(4*k4+3)*68 + m] = (y0.w+y1.w+y2.w)*siluf(z.w);
        }
        for (int f = tid; f < 768; f += 256){
            int cc = f >> 3, k4 = f & 7;
            float4 wv = *(const float4*)&W[cc*DI + kk + 4*k4];
            Ws2[(4*k4+0)*100 + cc] = wv.x;
            Ws2[(4*k4+1)*100 + cc] = wv.y;
            Ws2[(4*k4+2)*100 + cc] = wv.z;
            Ws2[(4*k4+3)*100 + cc] = wv.w;
        }
        __syncthreads();
        #pragma unroll 4
        for (int k = 0; k < 32; k++){
            float4 a = *(const float4*)&As[k*68 + 4*mg];
            float av[4] = {a.x, a.y, a.z, a.w};
            float wv[6];
            #pragma unroll
            for (int j = 0; j < 6; j++) wv[j] = Ws2[k*100 + 6*ng + j];
            #pragma unroll
            for (int i = 0; i < 4; i++)
                #pragma unroll
                for (int j = 0; j < 6; j++)
                    acc[i][j] = fmaf(av[i], wv[j], acc[i][j]);
        }
    }
    __syncthreads();
    #pragma unroll
    for (int i = 0; i < 4; i++)
        #pragma unroll
        for (int j = 0; j < 6; j++)
            Cs[(4*mg+i)*97 + 6*ng+j] = acc[i][j];
    __syncthreads();
    for (int f = tid; f < 64*96; f += 256){
        int cc = f >> 6, m = f & 63;
        int M = m0 + m;
        int b = M >> 9, l = M & 511;
        int hb = b >> 4, wb = (b >> 2) & 3, db = b & 3;
        int lh = l >> 6, lw = (l >> 3) & 7, ld = l & 7;
        int sp = (hb*8+lh)*1024 + (wb*8+lw)*32 + (db*8+ld);
        int oi = cc*NSPAT + sp;
        out[oi] = Cs[m*97 + cc] + x[oi];
    }
}

// ---------------- K7/K8/K9: ECA ----------------------------------------------
__global__ void mean_kernel(const float* __restrict__ out){
    __shared__ float red[256];
    int c = blockIdx.x;
    const float4* p = (const float4*)(out + (size_t)c*NSPAT);
    float s = 0.f;
    for (int i = threadIdx.x; i < NSPAT/4; i += 256){
        float4 v = p[i];
        s += (v.x + v.y) + (v.z + v.w);
    }
    red[threadIdx.x] = s; __syncthreads();
    for (int st = 128; st > 0; st >>= 1){
        if (threadIdx.x < st) red[threadIdx.x] += red[threadIdx.x + st];
        __syncthreads();
    }
    if (threadIdx.x == 0) g_mean[c] = red[0] * (1.f/NSPAT);
}

__global__ void gate_kernel(const float* __restrict__ ew){
    int c = threadIdx.x;
    if (c < CM){
        float m0 = (c > 0)    ? g_mean[c-1] : 0.f;
        float m1 = g_mean[c];
        float m2 = (c < CM-1) ? g_mean[c+1] : 0.f;
        float v = ew[0]*m0 + ew[1]*m1 + ew[2]*m2;
        g_gate[c] = 1.f / (1.f + __expf(-v));
    }
}

__global__ void scale_kernel(float* __restrict__ out){
    int i = blockIdx.x*256 + threadIdx.x;      // float4 index
    float g = g_gate[i >> 13];                 // 8192 float4 per channel
    float4* p = (float4*)out;
    float4 v = p[i];
    v.x *= g; v.y *= g; v.z *= g; v.w *= g;
    p[i] = v;
}

// -----------------------------------------------------------------------------
extern "C" void kernel_launch(void* const* d_in, const int* in_sizes, int n_in,
                              void* d_out, int out_size){
    const float* x   = (const float*)d_in[0];
    const float* lnw = (const float*)d_in[1];
    const float* lnb = (const float*)d_in[2];
    const float* ipw = (const float*)d_in[3];
    const float* opw = (const float*)d_in[4];
    int base, eca_idx;
    if (in_sizes[5] == 3) { eca_idx = 5;  base = 6; }
    else                  { base = 5;     eca_idx = 26; }
    const float* ecw = (const float*)d_in[eca_idx];
    const float *cw[3], *cb[3], *xp[3], *dw[3], *db[3], *Al[3], *Dp[3];
    for (int br = 0; br < 3; br++){
        const int o = base + 7*br;
        cw[br] = (const float*)d_in[o+0];
        cb[br] = (const float*)d_in[o+1];
        xp[br] = (const float*)d_in[o+2];
        dw[br] = (const float*)d_in[o+3];
        db[br] = (const float*)d_in[o+4];
        Al[br] = (const float*)d_in[o+5];
        Dp[br] = (const float*)d_in[o+6];
    }
    float* out = (float*)d_out;

    cudaFuncSetAttribute(ln_kernel,   cudaFuncAttributeMaxDynamicSharedMemorySize, 96*129*4);
    cudaFuncSetAttribute(xdbl_kernel, cudaFuncAttributeMaxDynamicSharedMemorySize, XDBL_SMEM);

    ln_kernel<<<NSPAT/128, 128, 96*129*4>>>(x, lnw, lnb);
    { dim3 g(NPOS/64, E2/64); inproj_kernel<<<g, 128>>>(ipw); }
    { dim3 g(4, WNB, 3); conv_kernel<<<g, DI>>>(cw[0],cb[0],cw[1],cb[1],cw[2],cb[2]); }
    { dim3 g(NPOS/128, 3);
      xdbl_kernel<<<g, 256, XDBL_SMEM>>>(xp[0],dw[0],db[0], xp[1],dw[1],db[1], xp[2],dw[2],db[2]); }
    { dim3 g(WNB, 2, 3); scan_kernel<<<g, 96>>>(Al[0],Dp[0],Al[1],Dp[1],Al[2],Dp[2]); }
    outproj_kernel<<<NPOS/64, 256>>>(opw, x, out);
    mean_kernel<<<CM, 256>>>(out);
    gate_kernel<<<1, 128>>>(ecw);
    scale_kernel<<<(CM*NSPAT/4)/256, 256>>>(out);
    (void)n_in; (void)out_size;
}

// round 4
// speedup vs baseline: 9.1350x; 1.1498x over previous
#include <cuda_runtime.h>
#include <math.h>

#define WNB   64
#define LSEQ  512
#define CM    96
#define DI    192
#define DS    16
#define E2    384
#define NPOS  (WNB*LSEQ)   // 32768
#define NSPAT 32768

// ---------------- scratch ----------------------------------------------------
__device__ __align__(16) float g_xn[NPOS*CM];
__device__ __align__(16) float g_xz[NPOS*E2];
__device__ __align__(16) float g_u[3][NPOS*DI];
__device__ __align__(16) float g_delta[3][NPOS*DI];
__device__ __align__(16) float g_Bm[3][NPOS*DS];
__device__ __align__(16) float g_Cm[3][NPOS*DS];
__device__ __align__(16) float g_y[3][NPOS*DI];
__device__ float g_mean[CM];
__device__ float g_gate[CM];

__device__ __forceinline__ float siluf(float v){ return v / (1.f + __expf(-v)); }
__device__ __forceinline__ float softplusf(float v){ return v > 15.f ? v : __logf(1.f + __expf(v)); }

typedef unsigned long long ull;
__device__ __forceinline__ ull fma2(ull a, ull b, ull c){
    ull d; asm("fma.rn.f32x2 %0, %1, %2, %3;" : "=l"(d) : "l"(a), "l"(b), "l"(c)); return d;
}
__device__ __forceinline__ ull mul2(ull a, ull b){
    ull d; asm("mul.rn.f32x2 %0, %1, %2;" : "=l"(d) : "l"(a), "l"(b)); return d;
}
__device__ __forceinline__ ull pack2(float lo, float hi){
    ull d; asm("mov.b64 %0, {%1, %2};" : "=l"(d) : "f"(lo), "f"(hi)); return d;
}
__device__ __forceinline__ float2 unpack2(ull v){
    float2 r; asm("mov.b64 {%0, %1}, %2;" : "=f"(r.x), "=f"(r.y) : "l"(v)); return r;
}
__device__ __forceinline__ ull splat2(float v){ return pack2(v, v); }

__device__ __forceinline__ int perm_idx(int br, int t){
    if (br == 0) return t;
    if (br == 1) return 511 - t;
    return ((t & 7) << 6) + (t >> 3);
}

// ---------------- K1: layernorm + window gather -------------------------------
__global__ void ln_kernel(const float* __restrict__ x,
                          const float* __restrict__ lnw,
                          const float* __restrict__ lnb){
    extern __shared__ float tile[];            // [96][129]
    __shared__ float s_mu[128], s_rs[128];
    __shared__ int   s_m[128];
    __shared__ float s_w[96], s_b[96];
    int tid = threadIdx.x;                     // 128
    int s0  = blockIdx.x * 128;
    if (tid < 96){ s_w[tid] = lnw[tid]; s_b[tid] = lnb[tid]; }
    int s = s0 + tid;
    float sum = 0.f, sq = 0.f;
    #pragma unroll 4
    for (int c = 0; c < 96; c++){
        float v = x[c*NSPAT + s];
        tile[c*129 + tid] = v;
        sum += v; sq = fmaf(v, v, sq);
    }
    float mu  = sum * (1.f/96);
    float var = sq  * (1.f/96) - mu*mu;
    s_mu[tid] = mu;
    s_rs[tid] = rsqrtf(var + 1e-5f);
    int h = s >> 10, w = (s >> 5) & 31, dd = s & 31;
    int b = (h>>3)*16 + (w>>3)*4 + (dd>>3);
    int l = (h&7)*64 + (w&7)*8 + (dd&7);
    s_m[tid] = b*LSEQ + l;
    __syncthreads();
    #pragma unroll 4
    for (int i = 0; i < 96; i++){
        int f = i*128 + tid;
        int c = f % 96, r = f / 96;
        float v = tile[c*129 + r];
        g_xn[s_m[r]*96 + c] = (v - s_mu[r])*s_rs[r]*s_w[c] + s_b[c];
    }
}

// ---------------- K2: in_proj GEMM (f32x2, pairs along n) ---------------------
__global__ void inproj_kernel(const float* __restrict__ W){
    __shared__ float As[48*92];
    __shared__ float Ws[48*92];
    int tid = threadIdx.x;            // 128
    int m0 = blockIdx.x * 64;
    int n0 = blockIdx.y * 64;
    ull acc2[4][4];
    #pragma unroll
    for (int i = 0; i < 4; i++)
        #pragma unroll
        for (int j = 0; j < 4; j++) acc2[i][j] = 0ull;
    int lr = tid & 15;        // 4 m rows each
    int nr = tid >> 4;        // 8 n each (4 pairs)
    for (int kk = 0; kk < 96; kk += 48){
        __syncthreads();
        #pragma unroll
        for (int j = 0; j < 6; j++){
            int f = tid + j*128;
            int row = f / 12, kq = f % 12;
            int sw = 4*(kq & 7);
            float4 a = *(const float4*)&g_xn[(m0+row)*96 + kk + kq*4];
            As[(kq*4+0)*92 + row + sw] = a.x; As[(kq*4+1)*92 + row + sw] = a.y;
            As[(kq*4+2)*92 + row + sw] = a.z; As[(kq*4+3)*92 + row + sw] = a.w;
            float4 bvec = *(const float4*)&W[(n0+row)*96 + kk + kq*4];
            Ws[(kq*4+0)*92 + row + sw] = bvec.x; Ws[(kq*4+1)*92 + row + sw] = bvec.y;
            Ws[(kq*4+2)*92 + row + sw] = bvec.z; Ws[(kq*4+3)*92 + row + sw] = bvec.w;
        }
        __syncthreads();
        #pragma unroll 4
        for (int k = 0; k < 48; k++){
            int sw = 4*((k>>2) & 7);
            float4 a  = *(const float4*)&As[k*92 + 4*lr + sw];
            float4 b0 = *(const float4*)&Ws[k*92 + 8*nr + sw];
            float4 b1 = *(const float4*)&Ws[k*92 + 8*nr + 4 + sw];
            ull bu[4] = { pack2(b0.x, b0.y), pack2(b0.z, b0.w),
                          pack2(b1.x, b1.y), pack2(b1.z, b1.w) };
            ull pa[4] = { splat2(a.x), splat2(a.y), splat2(a.z), splat2(a.w) };
            #pragma unroll
            for (int i = 0; i < 4; i++)
                #pragma unroll
                for (int j = 0; j < 4; j++)
                    acc2[i][j] = fma2(pa[i], bu[j], acc2[i][j]);
        }
    }
    #pragma unroll
    for (int i = 0; i < 4; i++){
        float2 p0 = unpack2(acc2[i][0]), p1 = unpack2(acc2[i][1]);
        float2 p2 = unpack2(acc2[i][2]), p3 = unpack2(acc2[i][3]);
        float* dst = &g_xz[(size_t)(m0 + 4*lr + i)*E2 + n0 + 8*nr];
        *(float4*)dst       = make_float4(p0.x, p0.y, p1.x, p1.y);
        *(float4*)(dst + 4) = make_float4(p2.x, p2.y, p3.x, p3.y);
    }
}

// ---------------- K3: causal conv4 + SiLU -------------------------------------
__global__ void conv_kernel(const float* __restrict__ cw0, const float* __restrict__ cb0,
                            const float* __restrict__ cw1, const float* __restrict__ cb1,
                            const float* __restrict__ cw2, const float* __restrict__ cb2){
    int d   = threadIdx.x;            // 0..191
    int tc  = blockIdx.x;             // 0..3
    int b   = blockIdx.y;             // 0..63
    int br  = blockIdx.z;             // 0..2
    const float* cw = (br == 0) ? cw0 : (br == 1) ? cw1 : cw2;
    const float* cb = (br == 0) ? cb0 : (br == 1) ? cb1 : cb2;
    float w0 = cw[d*4+0], w1 = cw[d*4+1], w2 = cw[d*4+2], w3 = cw[d*4+3];
    float bias = cb[d];
    const float* xb = g_xz + (size_t)b*LSEQ*E2 + d;
    float* ub = g_u[br] + (size_t)(b*LSEQ)*DI + d;
    int t0 = tc*128;
    float x1 = 0.f, x2 = 0.f, x3 = 0.f;
    if (t0 >= 1) x1 = xb[perm_idx(br, t0-1)*E2];
    if (t0 >= 2) x2 = xb[perm_idx(br, t0-2)*E2];
    if (t0 >= 3) x3 = xb[perm_idx(br, t0-3)*E2];
    float pf[8];
    #pragma unroll
    for (int j = 0; j < 8; j++) pf[j] = xb[perm_idx(br, t0+j)*E2];
    #pragma unroll 8
    for (int i = 0; i < 128; i++){
        int t = t0 + i;
        float xv = pf[i & 7];
        int tn = t + 8;
        if (tn < (tc+1)*128 + 8 && tn < LSEQ) pf[i & 7] = xb[perm_idx(br, tn)*E2];
        float acc = bias;
        acc = fmaf(w0, x3, acc);
        acc = fmaf(w1, x2, acc);
        acc = fmaf(w2, x1, acc);
        acc = fmaf(w3, xv, acc);
        ub[t*DI] = siluf(acc);
        x3 = x2; x2 = x1; x1 = xv;
    }
}

// ---------------- K4: x_dbl GEMM + delta + B/C  (f32x2, M-tile 256) -----------
// smem: ws_c[32][45] | us[32][284] (swizzled)  -> overlaid by xds[256][41]
#define XDBL_SMEM ((1440 + 32*284)*4)     // 42112 B
__global__ void xdbl_kernel(const float* __restrict__ xp0, const float* __restrict__ dw0, const float* __restrict__ db0,
                            const float* __restrict__ xp1, const float* __restrict__ dw1, const float* __restrict__ db1,
                            const float* __restrict__ xp2, const float* __restrict__ dw2, const float* __restrict__ db2){
    extern __shared__ float sm[];
    float* ws_c = sm;                 // [32][45]
    float* us   = sm + 1440;          // [32][284]
    float* xds  = sm;                 // epilogue overlay: [256][41]
    int tid = threadIdx.x;            // 256
    int br  = blockIdx.y;
    int m0  = blockIdx.x * 256;
    const float* xpw = (br == 0) ? xp0 : (br == 1) ? xp1 : xp2;
    const float* dtw = (br == 0) ? dw0 : (br == 1) ? dw1 : dw2;
    const float* dtb = (br == 0) ? db0 : (br == 1) ? db1 : db2;
    const float* gu = g_u[br];
    int mg = tid & 31;      // 8 m rows (4 pairs)
    int rg = tid >> 5;      // 5 r cols
    ull acc2[4][5];
    #pragma unroll
    for (int i = 0; i < 4; i++)
        #pragma unroll
        for (int j = 0; j < 5; j++) acc2[i][j] = 0ull;
    for (int kk = 0; kk < 192; kk += 32){
        __syncthreads();
        // stage weights [k][r] (+ zero pad rows 38..44)
        for (int f = tid; f < 304; f += 256){
            int r = f >> 3, k4 = f & 7;
            float4 v = *(const float4*)&xpw[r*192 + kk + 4*k4];
            ws_c[(4*k4+0)*45 + r] = v.x;
            ws_c[(4*k4+1)*45 + r] = v.y;
            ws_c[(4*k4+2)*45 + r] = v.z;
            ws_c[(4*k4+3)*45 + r] = v.w;
        }
        if (tid < 224){ int k = tid / 7, r = 38 + tid % 7; ws_c[k*45 + r] = 0.f; }
        // stage u chunk transposed+swizzled: col = m + 4*k4
        for (int f = tid; f < 2048; f += 256){
            int m = f >> 3, k4 = f & 7;
            float4 v = *(const float4*)&gu[(size_t)(m0+m)*192 + kk + 4*k4];
            int col = m + 4*k4;
            us[(4*k4+0)*284 + col] = v.x;
            us[(4*k4+1)*284 + col] = v.y;
            us[(4*k4+2)*284 + col] = v.z;
            us[(4*k4+3)*284 + col] = v.w;
        }
        __syncthreads();
        #pragma unroll 4
        for (int k = 0; k < 32; k++){
            int sw = 4*(k >> 2);
            float4 a0 = *(const float4*)&us[k*284 + 8*mg + sw];
            float4 a1 = *(const float4*)&us[k*284 + 8*mg + 4 + sw];
            ull au[4] = { pack2(a0.x, a0.y), pack2(a0.z, a0.w),
                          pack2(a1.x, a1.y), pack2(a1.z, a1.w) };
            const float* wr = &ws_c[k*45 + 5*rg];
            ull wv[5] = { splat2(wr[0]), splat2(wr[1]), splat2(wr[2]),
                          splat2(wr[3]), splat2(wr[4]) };
            #pragma unroll
            for (int i = 0; i < 4; i++)
                #pragma unroll
                for (int j = 0; j < 5; j++)
                    acc2[i][j] = fma2(au[i], wv[j], acc2[i][j]);
        }
    }
    __syncthreads();
    #pragma unroll
    for (int i = 0; i < 4; i++)
        #pragma unroll
        for (int j = 0; j < 5; j++){
            float2 p = unpack2(acc2[i][j]);
            xds[(8*mg + 2*i    )*41 + 5*rg + j] = p.x;
            xds[(8*mg + 2*i + 1)*41 + 5*rg + j] = p.y;
        }
    __syncthreads();
    // scatter B, C
    float* gB = g_Bm[br];
    float* gC = g_Cm[br];
    for (int f = tid; f < 256*32; f += 256){
        int m = f >> 5, j = f & 31;
        float v = xds[m*41 + 6 + j];
        if (j < 16) gB[(size_t)(m0+m)*DS + j]      = v;
        else        gC[(size_t)(m0+m)*DS + (j-16)] = v;
    }
    // delta
    if (tid < 192){
        float dwr[6];
        #pragma unroll
        for (int r = 0; r < 6; r++) dwr[r] = dtw[tid*6 + r];
        float db_ = dtb[tid];
        float* gD = g_delta[br];
        #pragma unroll 2
        for (int m = 0; m < 256; m++){
            float acc = db_;
            #pragma unroll
            for (int r = 0; r < 6; r++)
                acc = fmaf(xds[m*41 + r], dwr[r], acc);
            gD[(size_t)(m0+m)*DI + tid] = softplusf(acc);
        }
    }
}

// ---------------- K5: selective scan (f32x2 + power-tree exp) -----------------
__global__ void scan_kernel(const float* __restrict__ Al0, const float* __restrict__ Dp0,
                            const float* __restrict__ Al1, const float* __restrict__ Dp1,
                            const float* __restrict__ Al2, const float* __restrict__ Dp2){
    __shared__ float sd[16*96];
    __shared__ float su[16*96];
    __shared__ __align__(16) float sB[16*16];
    __shared__ __align__(16) float sC[16*16];
    int tid  = threadIdx.x;           // 0..95
    int b    = blockIdx.x;
    int half = blockIdx.y;
    int br   = blockIdx.z;
    int d    = half*96 + tid;
    const float* Alog = (br == 0) ? Al0 : (br == 1) ? Al1 : Al2;
    const float* Dp   = (br == 0) ? Dp0 : (br == 1) ? Dp1 : Dp2;
    float Ar[16];
    #pragma unroll
    for (int s = 0; s < 16; s++) Ar[s] = -__expf(Alog[d*16 + s]);
    bool fast = true;
    #pragma unroll
    for (int s = 0; s < 16; s++)
        fast = fast && (fabsf(Ar[s] + (float)(s+1)) < 1e-3f*(float)(s+1));
    float Ar0 = Ar[0];
    float Dd = Dp[d];
    ull h2[8];
    #pragma unroll
    for (int s = 0; s < 8; s++) h2[s] = 0ull;
    float hs[16];
    #pragma unroll
    for (int s = 0; s < 16; s++) hs[s] = 0.f;
    const float* gdp = g_delta[br] + (size_t)(b*LSEQ)*DI + d;
    const float* gup = g_u[br]     + (size_t)(b*LSEQ)*DI + d;
    const float* gBp = g_Bm[br]    + (size_t)(b*LSEQ)*DS;
    const float* gCp = g_Cm[br]    + (size_t)(b*LSEQ)*DS;
    float* yb = g_y[br] + (size_t)(b*LSEQ)*DI + d;
    float pd[16], pu[16], pb[3], pc[3];
    #pragma unroll
    for (int i = 0; i < 16; i++){ pd[i] = gdp[i*DI]; pu[i] = gup[i*DI]; }
    #pragma unroll
    for (int i = 0; i < 3; i++){
        int idx = i*96 + tid;
        pb[i] = (idx < 256) ? gBp[idx] : 0.f;
        pc[i] = (idx < 256) ? gCp[idx] : 0.f;
    }
    for (int c = 0; c < 32; c++){
        #pragma unroll
        for (int i = 0; i < 16; i++){ sd[i*96+tid] = pd[i]; su[i*96+tid] = pu[i]; }
        #pragma unroll
        for (int i = 0; i < 3; i++){
            int idx = i*96 + tid;
            if (idx < 256){ sB[idx] = pb[i]; sC[idx] = pc[i]; }
        }
        __syncthreads();
        if (c + 1 < 32){
            size_t ofs = (size_t)(c+1)*16*DI;
            #pragma unroll
            for (int i = 0; i < 16; i++){ pd[i] = gdp[ofs + i*DI]; pu[i] = gup[ofs + i*DI]; }
            int ofb = (c+1)*256;
            #pragma unroll
            for (int i = 0; i < 3; i++){
                int idx = i*96 + tid;
                if (idx < 256){ pb[i] = gBp[ofb + idx]; pc[i] = gCp[ofb + idx]; }
            }
        }
        if (fast){
            for (int t2 = 0; t2 < 16; t2++){
                float delta = sd[t2*96 + tid];
                float u     = su[t2*96 + tid];
                float du    = delta * u;
                float q  = __expf(delta * Ar0);
                float q2 = q*q;
                ull v0 = pack2(q, q2);
                ull s2 = pack2(q2, q2);
                ull v1 = mul2(v0, s2);
                float q4 = unpack2(v1).y;
                ull s4 = pack2(q4, q4);
                ull v2 = mul2(v0, s4);
                ull v3 = mul2(v1, s4);
                float q8 = unpack2(v3).y;
                ull s8 = pack2(q8, q8);
                ull pw[8] = {v0, v1, v2, v3,
                             mul2(v0, s8), mul2(v1, s8), mul2(v2, s8), mul2(v3, s8)};
                ull du2 = pack2(du, du);
                const ulonglong2* B2 = (const ulonglong2*)(sB + t2*16);
                const ulonglong2* C2 = (const ulonglong2*)(sC + t2*16);
                ull y2 = 0ull;
                #pragma unroll
                for (int i = 0; i < 4; i++){
                    ulonglong2 Bv = B2[i];
                    ulonglong2 Cv = C2[i];
                    h2[2*i]   = fma2(h2[2*i],   pw[2*i],   mul2(Bv.x, du2));
                    y2 = fma2(h2[2*i], Cv.x, y2);
                    h2[2*i+1] = fma2(h2[2*i+1], pw[2*i+1], mul2(Bv.y, du2));
                    y2 = fma2(h2[2*i+1], Cv.y, y2);
                }
                float2 yy = unpack2(y2);
                int t = c*16 + t2;
                yb[perm_idx(br, t)*DI] = fmaf(Dd, u, yy.x + yy.y);
            }
        } else {
            for (int t2 = 0; t2 < 16; t2++){
                float delta = sd[t2*96 + tid];
                float u     = su[t2*96 + tid];
                float du    = delta * u;
                float y = 0.f;
                #pragma unroll
                for (int s = 0; s < 16; s++){
                    float dA = __expf(delta * Ar[s]);
                    hs[s] = fmaf(hs[s], dA, du * sB[t2*16 + s]);
                    y     = fmaf(hs[s], sC[t2*16 + s], y);
                }
                int t = c*16 + t2;
                yb[perm_idx(br, t)*DI] = fmaf(Dd, u, y);
            }
        }
        __syncthreads();
    }
}

// ---------------- K6: combine*silu(z) + out_proj (f32x2) + reverse + residual -
// smem: mainloop As[32][92] + Ws2[32][124]; epilogue Cs[64][100] overlays
#define OUTP_SMEM ((32*92 + 32*124)*4)    // 27648 B (>= Cs 25600)
__global__ void outproj_kernel(const float* __restrict__ W,
                               const float* __restrict__ x,
                               float* __restrict__ out){
    extern __shared__ float sm2[];
    float* As  = sm2;                 // [32][92]
    float* Ws2 = sm2 + 32*92;         // [32][124]
    float* Cs  = sm2;                 // epilogue overlay [64][100]
    int tid = threadIdx.x;            // 128
    int m0 = blockIdx.x * 64;
    int mg = tid & 15;                // 4 m rows
    int ng = tid >> 4;                // 12 c cols (6 pairs)
    ull acc2[4][6];
    #pragma unroll
    for (int i = 0; i < 4; i++)
        #pragma unroll
        for (int j = 0; j < 6; j++) acc2[i][j] = 0ull;
    for (int kk = 0; kk < 192; kk += 32){
        __syncthreads();
        for (int f = tid; f < 512; f += 128){
            int m = f >> 3, k4 = f & 7;
            size_t mi = (size_t)(m0+m)*DI + kk + 4*k4;
            float4 y0 = *(const float4*)&g_y[0][mi];
            float4 y1 = *(const float4*)&g_y[1][mi];
            float4 y2 = *(const float4*)&g_y[2][mi];
            float4 z  = *(const float4*)&g_xz[(size_t)(m0+m)*E2 + DI + kk + 4*k4];
            int col = m + 4*k4;
            As[(4*k4+0)*92 + col] = (y0.x+y1.x+y2.x)*siluf(z.x);
            As[(4*k4+1)*92 + col] = (y0.y+y1.y+y2.y)*siluf(z.y);
            As[(4*k4+2)*92 + col] = (y0.z+y1.z+y2.z)*siluf(z.z);
            As[(4*k4+3)*92 + col] = (y0.w+y1.w+y2.w)*siluf(z.w);
        }
        for (int f = tid; f < 768; f += 128){
            int cc = f >> 3, k4 = f & 7;
            float4 wv = *(const float4*)&W[cc*DI + kk + 4*k4];
            int col = cc + 4*k4;
            Ws2[(4*k4+0)*124 + col] = wv.x;
            Ws2[(4*k4+1)*124 + col] = wv.y;
            Ws2[(4*k4+2)*124 + col] = wv.z;
            Ws2[(4*k4+3)*124 + col] = wv.w;
        }
        __syncthreads();
        #pragma unroll 4
        for (int k = 0; k < 32; k++){
            int sw = 4*(k >> 2);
            float4 a = *(const float4*)&As[k*92 + 4*mg + sw];
            ull pa[4] = { splat2(a.x), splat2(a.y), splat2(a.z), splat2(a.w) };
            float4 b0 = *(const float4*)&Ws2[k*124 + 12*ng + sw];
            float4 b1 = *(const float4*)&Ws2[k*124 + 12*ng + 4 + sw];
            float4 b2 = *(const float4*)&Ws2[k*124 + 12*ng + 8 + sw];
            ull bu[6] = { pack2(b0.x,b0.y), pack2(b0.z,b0.w),
                          pack2(b1.x,b1.y), pack2(b1.z,b1.w),
                          pack2(b2.x,b2.y), pack2(b2.z,b2.w) };
            #pragma unroll
            for (int i = 0; i < 4; i++)
                #pragma unroll
                for (int j = 0; j < 6; j++)
                    acc2[i][j] = fma2(pa[i], bu[j], acc2[i][j]);
        }
    }
    __syncthreads();
    #pragma unroll
    for (int i = 0; i < 4; i++){
        float2 p0 = unpack2(acc2[i][0]), p1 = unpack2(acc2[i][1]);
        float2 p2 = unpack2(acc2[i][2]), p3 = unpack2(acc2[i][3]);
        float2 p4 = unpack2(acc2[i][4]), p5 = unpack2(acc2[i][5]);
        float* dst = &Cs[(4*mg+i)*100 + 12*ng];
        *(float4*)(dst    ) = make_float4(p0.x, p0.y, p1.x, p1.y);
        *(float4*)(dst + 4) = make_float4(p2.x, p2.y, p3.x, p3.y);
        *(float4*)(dst + 8) = make_float4(p4.x, p4.y, p5.x, p5.y);
    }
    __syncthreads();
    for (int f = tid; f < 64*96; f += 128){
        int cc = f >> 6, m = f & 63;
        int M = m0 + m;
        int b = M >> 9, l = M & 511;
        int hb = b >> 4, wb = (b >> 2) & 3, db = b & 3;
        int lh = l >> 6, lw = (l >> 3) & 7, ld = l & 7;
        int sp = (hb*8+lh)*1024 + (wb*8+lw)*32 + (db*8+ld);
        int oi = cc*NSPAT + sp;
        out[oi] = Cs[m*100 + cc] + x[oi];
    }
}

// ---------------- K7/K8/K9: ECA ----------------------------------------------
__global__ void mean_kernel(const float* __restrict__ out){
    __shared__ float red[256];
    int c = blockIdx.x;
    const float4* p = (const float4*)(out + (size_t)c*NSPAT);
    float s = 0.f;
    for (int i = threadIdx.x; i < NSPAT/4; i += 256){
        float4 v = p[i];
        s += (v.x + v.y) + (v.z + v.w);
    }
    red[threadIdx.x] = s; __syncthreads();
    for (int st = 128; st > 0; st >>= 1){
        if (threadIdx.x < st) red[threadIdx.x] += red[threadIdx.x + st];
        __syncthreads();
    }
    if (threadIdx.x == 0) g_mean[c] = red[0] * (1.f/NSPAT);
}

__global__ void gate_kernel(const float* __restrict__ ew){
    int c = threadIdx.x;
    if (c < CM){
        float m0 = (c > 0)    ? g_mean[c-1] : 0.f;
        float m1 = g_mean[c];
        float m2 = (c < CM-1) ? g_mean[c+1] : 0.f;
        float v = ew[0]*m0 + ew[1]*m1 + ew[2]*m2;
        g_gate[c] = 1.f / (1.f + __expf(-v));
    }
}

__global__ void scale_kernel(float* __restrict__ out){
    int i = blockIdx.x*256 + threadIdx.x;
    float g = g_gate[i >> 13];
    float4* p = (float4*)out;
    float4 v = p[i];
    v.x *= g; v.y *= g; v.z *= g; v.w *= g;
    p[i] = v;
}

// -----------------------------------------------------------------------------
extern "C" void kernel_launch(void* const* d_in, const int* in_sizes, int n_in,
                              void* d_out, int out_size){
    const float* x   = (const float*)d_in[0];
    const float* lnw = (const float*)d_in[1];
    const float* lnb = (const float*)d_in[2];
    const float* ipw = (const float*)d_in[3];
    const float* opw = (const float*)d_in[4];
    int base, eca_idx;
    if (in_sizes[5] == 3) { eca_idx = 5;  base = 6; }
    else                  { base = 5;     eca_idx = 26; }
    const float* ecw = (const float*)d_in[eca_idx];
    const float *cw[3], *cb[3], *xp[3], *dw[3], *db[3], *Al[3], *Dp[3];
    for (int br = 0; br < 3; br++){
        const int o = base + 7*br;
        cw[br] = (const float*)d_in[o+0];
        cb[br] = (const float*)d_in[o+1];
        xp[br] = (const float*)d_in[o+2];
        dw[br] = (const float*)d_in[o+3];
        db[br] = (const float*)d_in[o+4];
        Al[br] = (const float*)d_in[o+5];
        Dp[br] = (const float*)d_in[o+6];
    }
    float* out = (float*)d_out;

    cudaFuncSetAttribute(ln_kernel,      cudaFuncAttributeMaxDynamicSharedMemorySize, 96*129*4);
    cudaFuncSetAttribute(xdbl_kernel,    cudaFuncAttributeMaxDynamicSharedMemorySize, XDBL_SMEM);
    cudaFuncSetAttribute(outproj_kernel, cudaFuncAttributeMaxDynamicSharedMemorySize, OUTP_SMEM);

    ln_kernel<<<NSPAT/128, 128, 96*129*4>>>(x, lnw, lnb);
    { dim3 g(NPOS/64, E2/64); inproj_kernel<<<g, 128>>>(ipw); }
    { dim3 g(4, WNB, 3); conv_kernel<<<g, DI>>>(cw[0],cb[0],cw[1],cb[1],cw[2],cb[2]); }
    { dim3 g(NPOS/256, 3);
      xdbl_kernel<<<g, 256, XDBL_SMEM>>>(xp[0],dw[0],db[0], xp[1],dw[1],db[1], xp[2],dw[2],db[2]); }
    { dim3 g(WNB, 2, 3); scan_kernel<<<g, 96>>>(Al[0],Dp[0],Al[1],Dp[1],Al[2],Dp[2]); }
    outproj_kernel<<<NPOS/64, 128, OUTP_SMEM>>>(opw, x, out);
    mean_kernel<<<CM, 256>>>(out);
    gate_kernel<<<1, 128>>>(ecw);
    scale_kernel<<<(CM*NSPAT/4)/256, 256>>>(out);
    (void)n_in; (void)out_size;
}